// round 11
// baseline (speedup 1.0000x reference)
#include <cuda_runtime.h>
#include <math.h>

// Normalized W lives here: 2 rows x 512 cols
__device__ float g_Wn[2 * 512];

static constexpr float EPS_CLIP = 1e-7f;
static constexpr float SCALE    = 64.0f;
// cos(0.5), sin(0.5)
static constexpr float COS_M = 0.8775825618903728f;
static constexpr float SIN_M = 0.479425538604203f;

// ---------------------------------------------------------------------------
// Prologue: L2-normalize W rows (C=2, D=512) into g_Wn. Fires PDL so the
// main grid launches immediately and overlaps this kernel.
// ---------------------------------------------------------------------------
__global__ void normalize_w_kernel(const float* __restrict__ W) {
    asm volatile("griddepcontrol.launch_dependents;" ::: "memory");

    const int row = blockIdx.x;            // 0 or 1
    const int tid = threadIdx.x;           // 0..127
    const float* wrow = W + row * 512;

    float ss = 0.0f;
    #pragma unroll
    for (int i = tid; i < 512; i += 128) {
        float v = wrow[i];
        ss += v * v;
    }
    #pragma unroll
    for (int o = 16; o > 0; o >>= 1) ss += __shfl_xor_sync(0xffffffff, ss, o);

    __shared__ float warp_ss[4];
    __shared__ float s_inv;
    const int lane = tid & 31;
    const int wid  = tid >> 5;
    if (lane == 0) warp_ss[wid] = ss;
    __syncthreads();
    if (tid == 0) {
        float tot = warp_ss[0] + warp_ss[1] + warp_ss[2] + warp_ss[3];
        s_inv = 1.0f / fmaxf(sqrtf(tot), 1e-12f);
    }
    __syncthreads();

    const float inv = s_inv;
    #pragma unroll
    for (int i = tid; i < 512; i += 128) {
        g_Wn[row * 512 + i] = wrow[i] * inv;
    }
}

// ---------------------------------------------------------------------------
// Main: one warp per PAIR of adjacent feature rows (2g, 2g+1), no in-warp
// loop. 8 streaming feat LDG.128 front-batched (__ldcs), 8 W LDG.128 (L1
// hits) shared by both rows, 96 FMA, ONE 6-value reduce region, one int2
// label load and one STG.128 output store per pair.
// ---------------------------------------------------------------------------
__global__ void __launch_bounds__(256, 5)
arcface_kernel(const float* __restrict__ feat,
               const int*   __restrict__ label,
               float*       __restrict__ out,
               int npairs)
{
    const int pair = (blockIdx.x * blockDim.x + threadIdx.x) >> 5;
    const int lane = threadIdx.x & 31;
    if (pair >= npairs) return;

    const float4* __restrict__ fA =
        reinterpret_cast<const float4*>(feat + (size_t)pair * 1024);
    const float4* __restrict__ fB = fA + 128;   // next row

    // Front-batch 8 streaming loads (1 KB in flight per warp, evict-first).
    float4 a0 = __ldcs(&fA[lane]);
    float4 a1 = __ldcs(&fA[lane + 32]);
    float4 a2 = __ldcs(&fA[lane + 64]);
    float4 a3 = __ldcs(&fA[lane + 96]);
    float4 b0 = __ldcs(&fB[lane]);
    float4 b1 = __ldcs(&fB[lane + 32]);
    float4 b2 = __ldcs(&fB[lane + 64]);
    float4 b3 = __ldcs(&fB[lane + 96]);

    // Wait for the prologue's g_Wn writes (PDL).
    asm volatile("griddepcontrol.wait;" ::: "memory");

    const float4* __restrict__ w0 = reinterpret_cast<const float4*>(g_Wn);
    const float4* __restrict__ w1 = reinterpret_cast<const float4*>(g_Wn + 512);

    float ssA = 0.0f, d0A = 0.0f, d1A = 0.0f;
    float ssB = 0.0f, d0B = 0.0f, d1B = 0.0f;

    {
        float4 wb, wc;
        #define ACC2(A, Bv, K)                                                 \
            wb = w0[lane + 32 * (K)];                                          \
            wc = w1[lane + 32 * (K)];                                          \
            ssA = fmaf(A.x, A.x, ssA);  ssA = fmaf(A.y, A.y, ssA);             \
            ssA = fmaf(A.z, A.z, ssA);  ssA = fmaf(A.w, A.w, ssA);             \
            d0A = fmaf(A.x, wb.x, d0A); d0A = fmaf(A.y, wb.y, d0A);            \
            d0A = fmaf(A.z, wb.z, d0A); d0A = fmaf(A.w, wb.w, d0A);            \
            d1A = fmaf(A.x, wc.x, d1A); d1A = fmaf(A.y, wc.y, d1A);            \
            d1A = fmaf(A.z, wc.z, d1A); d1A = fmaf(A.w, wc.w, d1A);            \
            ssB = fmaf(Bv.x, Bv.x, ssB);  ssB = fmaf(Bv.y, Bv.y, ssB);         \
            ssB = fmaf(Bv.z, Bv.z, ssB);  ssB = fmaf(Bv.w, Bv.w, ssB);         \
            d0B = fmaf(Bv.x, wb.x, d0B); d0B = fmaf(Bv.y, wb.y, d0B);          \
            d0B = fmaf(Bv.z, wb.z, d0B); d0B = fmaf(Bv.w, wb.w, d0B);          \
            d1B = fmaf(Bv.x, wc.x, d1B); d1B = fmaf(Bv.y, wc.y, d1B);          \
            d1B = fmaf(Bv.z, wc.z, d1B); d1B = fmaf(Bv.w, wc.w, d1B);
        ACC2(a0, b0, 0)
        ACC2(a1, b1, 1)
        ACC2(a2, b2, 2)
        ACC2(a3, b3, 3)
        #undef ACC2
    }

    // One reduce region for both rows (6 chains pipeline together).
    #pragma unroll
    for (int o = 16; o > 0; o >>= 1) {
        ssA += __shfl_xor_sync(0xffffffff, ssA, o);
        d0A += __shfl_xor_sync(0xffffffff, d0A, o);
        d1A += __shfl_xor_sync(0xffffffff, d1A, o);
        ssB += __shfl_xor_sync(0xffffffff, ssB, o);
        d0B += __shfl_xor_sync(0xffffffff, d0B, o);
        d1B += __shfl_xor_sync(0xffffffff, d1B, o);
    }

    if (lane == 0) {
        const int2 lab = reinterpret_cast<const int2*>(label)[pair];

        const float invA = rsqrtf(fmaxf(ssA, 1e-24f));
        float c0 = fminf(fmaxf(d0A * invA, -1.0f + EPS_CLIP), 1.0f - EPS_CLIP);
        float c1 = fminf(fmaxf(d1A * invA, -1.0f + EPS_CLIP), 1.0f - EPS_CLIP);
        float s0 = sqrtf(fmaxf(1.0f - c0 * c0, 0.0f));
        float s1 = sqrtf(fmaxf(1.0f - c1 * c1, 0.0f));
        float oA0 = (lab.x == 0) ? (c0 * COS_M - s0 * SIN_M) : c0;
        float oA1 = (lab.x == 1) ? (c1 * COS_M - s1 * SIN_M) : c1;

        const float invB = rsqrtf(fmaxf(ssB, 1e-24f));
        float e0 = fminf(fmaxf(d0B * invB, -1.0f + EPS_CLIP), 1.0f - EPS_CLIP);
        float e1 = fminf(fmaxf(d1B * invB, -1.0f + EPS_CLIP), 1.0f - EPS_CLIP);
        float t0 = sqrtf(fmaxf(1.0f - e0 * e0, 0.0f));
        float t1 = sqrtf(fmaxf(1.0f - e1 * e1, 0.0f));
        float oB0 = (lab.y == 0) ? (e0 * COS_M - t0 * SIN_M) : e0;
        float oB1 = (lab.y == 1) ? (e1 * COS_M - t1 * SIN_M) : e1;

        reinterpret_cast<float4*>(out)[pair] =
            make_float4(oA0 * SCALE, oA1 * SCALE, oB0 * SCALE, oB1 * SCALE);
    }
}

// ---------------------------------------------------------------------------
// kernel_launch: identify inputs by element count (robust to ordering):
//   feat : B*D f32 (largest), W : C*D f32 (smallest), label : B int32
// B is even (131072) -> npairs = B/2. PDL launch for the main kernel.
// ---------------------------------------------------------------------------
extern "C" void kernel_launch(void* const* d_in, const int* in_sizes, int n_in,
                              void* d_out, int out_size)
{
    int i_feat = 0, i_w = 0, i_lab = 0;
    for (int i = 1; i < n_in; i++) {
        if (in_sizes[i] > in_sizes[i_feat]) i_feat = i;
        if (in_sizes[i] < in_sizes[i_w])    i_w    = i;
    }
    for (int i = 0; i < n_in; i++)
        if (i != i_feat && i != i_w) i_lab = i;

    const float* feat  = (const float*)d_in[i_feat];
    const float* W     = (const float*)d_in[i_w];
    const int*   label = (const int*)d_in[i_lab];
    float*       out   = (float*)d_out;
    const int    B     = in_sizes[i_lab];
    const int    npairs = B / 2;

    normalize_w_kernel<<<2, 128>>>(W);

    const int blocks = (npairs + 7) / 8;   // 8 pairs (warps) per block

    cudaLaunchConfig_t cfg = {};
    cfg.gridDim  = dim3((unsigned)blocks, 1, 1);
    cfg.blockDim = dim3(256, 1, 1);
    cfg.dynamicSmemBytes = 0;
    cfg.stream = 0;

    cudaLaunchAttribute attr[1];
    attr[0].id = cudaLaunchAttributeProgrammaticStreamSerialization;
    attr[0].val.programmaticStreamSerializationAllowed = 1;
    cfg.attrs = attr;
    cfg.numAttrs = 1;

    cudaLaunchKernelEx(&cfg, arcface_kernel, feat, label, out, npairs);
}